// round 2
// baseline (speedup 1.0000x reference)
#include <cuda_runtime.h>
#include <math.h>

// ---------------------------------------------------------------------------
// Shapes (fixed): L=12, E=128, H=4, D=32, F=512, B=64, CIN=256, N=257
// Tokens T = B*N = 16448
// ---------------------------------------------------------------------------
#define TOKENS 16448
#define EMB 128
#define NTOK 257
#define BATCH 64

// scratch (device globals; allocation is forbidden)
__device__ float g_x  [TOKENS * 128];   // residual stream
__device__ float g_h  [TOKENS * 128];   // post-LN
__device__ float g_qkv[TOKENS * 384];
__device__ float g_o  [TOKENS * 128];   // attention output
__device__ float g_ffn[TOKENS * 512];   // ffn hidden

__device__ __forceinline__ float warp_sum(float v) {
    #pragma unroll
    for (int o = 16; o; o >>= 1) v += __shfl_xor_sync(0xffffffffu, v, o);
    return v;
}
__device__ __forceinline__ float warp_max(float v) {
    #pragma unroll
    for (int o = 16; o; o >>= 1) v = fmaxf(v, __shfl_xor_sync(0xffffffffu, v, o));
    return v;
}

// ---------------------------------------------------------------------------
// Generic tiled SGEMM: C[M,N] = A[M,K] @ W[N,K]^T + bias, with fused epilogue.
// MODE 0: +bias   MODE 1: gelu(+bias)   MODE 2: +bias + res (res shape == C)
// M%64==0, N%64==0, K%32==0 guaranteed by the problem shapes.
// ---------------------------------------------------------------------------
#define TM 64
#define TN 64
#define TK 32

template <int MODE>
__global__ __launch_bounds__(256)
void gemm_kernel(const float* __restrict__ A, const float* __restrict__ W,
                 const float* __restrict__ bias, const float* __restrict__ res,
                 float* __restrict__ C, int M, int N, int K)
{
    __shared__ float As[TM][TK + 1];
    __shared__ float Bs[TN][TK + 1];
    const int tid = threadIdx.x;
    const int tx = tid & 15, ty = tid >> 4;
    const int m0 = blockIdx.y * TM, n0 = blockIdx.x * TN;

    float acc[4][4];
    #pragma unroll
    for (int i = 0; i < 4; i++)
        #pragma unroll
        for (int j = 0; j < 4; j++) acc[i][j] = 0.f;

    for (int k0 = 0; k0 < K; k0 += TK) {
        #pragma unroll
        for (int i = 0; i < 8; i++) {
            int id = tid + i * 256;          // 2048 elements per tile
            int m = id >> 5, k = id & 31;
            As[m][k] = A[(size_t)(m0 + m) * K + k0 + k];
            Bs[m][k] = W[(size_t)(n0 + m) * K + k0 + k];
        }
        __syncthreads();
        #pragma unroll
        for (int kk = 0; kk < TK; kk++) {
            float a[4], b[4];
            #pragma unroll
            for (int i = 0; i < 4; i++) a[i] = As[ty * 4 + i][kk];
            #pragma unroll
            for (int j = 0; j < 4; j++) b[j] = Bs[tx * 4 + j][kk];
            #pragma unroll
            for (int i = 0; i < 4; i++)
                #pragma unroll
                for (int j = 0; j < 4; j++) acc[i][j] += a[i] * b[j];
        }
        __syncthreads();
    }

    #pragma unroll
    for (int i = 0; i < 4; i++) {
        int m = m0 + ty * 4 + i;
        #pragma unroll
        for (int j = 0; j < 4; j++) {
            int n = n0 + tx * 4 + j;
            float v = acc[i][j] + bias[n];
            if (MODE == 1) v = v * 0.5f * (1.0f + erff(v * 0.70710678118654752f));
            if (MODE == 2) v += res[(size_t)m * N + n];
            C[(size_t)m * N + n] = v;
        }
    }
}

// ---------------------------------------------------------------------------
// Conv 3x3 stride 2 pad 1 as implicit GEMM: M=16384 pixels, N=128, K=2304.
// Epilogue writes directly into the token buffer g_x at row b*257+p+1 with
// conv bias + positional embedding fused.
// ---------------------------------------------------------------------------
__global__ __launch_bounds__(256)
void conv_kernel(const float* __restrict__ feat, const float* __restrict__ W,
                 const float* __restrict__ cb, const float* __restrict__ pos,
                 float* __restrict__ x)
{
    __shared__ float As[TM][TK + 1];
    __shared__ float Bs[TN][TK + 1];
    const int K = 2304;
    const int tid = threadIdx.x;
    const int tx = tid & 15, ty = tid >> 4;
    const int m0 = blockIdx.y * TM, n0 = blockIdx.x * TN;

    float acc[4][4];
    #pragma unroll
    for (int i = 0; i < 4; i++)
        #pragma unroll
        for (int j = 0; j < 4; j++) acc[i][j] = 0.f;

    for (int k0 = 0; k0 < K; k0 += TK) {
        #pragma unroll
        for (int i = 0; i < 8; i++) {
            int id = tid + i * 256;
            int ml = id >> 5, kl = id & 31;
            int m = m0 + ml;
            int k = k0 + kl;
            int b = m >> 8, p = m & 255;
            int y = p >> 4, xx = p & 15;
            int c = k / 9, r = k - c * 9;
            int ky = r / 3, kx = r - ky * 3;
            int iy = y * 2 - 1 + ky;
            int ix = xx * 2 - 1 + kx;
            float v = 0.f;
            if (iy >= 0 && iy < 32 && ix >= 0 && ix < 32)
                v = feat[(((size_t)b * 256 + c) * 32 + iy) * 32 + ix];
            As[ml][kl] = v;
            Bs[ml][kl] = W[(size_t)(n0 + ml) * K + k];
        }
        __syncthreads();
        #pragma unroll
        for (int kk = 0; kk < TK; kk++) {
            float a[4], b[4];
            #pragma unroll
            for (int i = 0; i < 4; i++) a[i] = As[ty * 4 + i][kk];
            #pragma unroll
            for (int j = 0; j < 4; j++) b[j] = Bs[tx * 4 + j][kk];
            #pragma unroll
            for (int i = 0; i < 4; i++)
                #pragma unroll
                for (int j = 0; j < 4; j++) acc[i][j] += a[i] * b[j];
        }
        __syncthreads();
    }

    #pragma unroll
    for (int i = 0; i < 4; i++) {
        int m = m0 + ty * 4 + i;
        int b = m >> 8, p = m & 255;
        #pragma unroll
        for (int j = 0; j < 4; j++) {
            int n = n0 + tx * 4 + j;
            float v = acc[i][j] + cb[n] + pos[(size_t)(p + 1) * 128 + n];
            x[((size_t)b * NTOK + p + 1) * 128 + n] = v;
        }
    }
}

// cls token rows: x[b,0,:] = cls + pos[0]
__global__ void cls_kernel(const float* __restrict__ cls,
                           const float* __restrict__ pos, float* __restrict__ x)
{
    int b = blockIdx.x, e = threadIdx.x;
    x[(size_t)b * NTOK * 128 + e] = cls[e] + pos[e];
}

// ---------------------------------------------------------------------------
// LayerNorm over E=128: 8 warps/block, 1 warp per token, float4 lanes.
// ---------------------------------------------------------------------------
__global__ __launch_bounds__(256)
void ln_kernel(const float* __restrict__ x, float* __restrict__ h,
               const float* __restrict__ s, const float* __restrict__ b, float eps)
{
    int tok = blockIdx.x * 8 + (threadIdx.x >> 5);
    int lane = threadIdx.x & 31;
    if (tok >= TOKENS) return;
    const float4* xr = (const float4*)(x + (size_t)tok * 128);
    float4 v = xr[lane];
    float mean = warp_sum(v.x + v.y + v.z + v.w) * (1.f / 128.f);
    float dx = v.x - mean, dy = v.y - mean, dz = v.z - mean, dw = v.w - mean;
    float var = warp_sum(dx * dx + dy * dy + dz * dz + dw * dw) * (1.f / 128.f);
    float rstd = rsqrtf(var + eps);
    float4 sv = ((const float4*)s)[lane];
    float4 bv = ((const float4*)b)[lane];
    float4 o;
    o.x = dx * rstd * sv.x + bv.x;
    o.y = dy * rstd * sv.y + bv.y;
    o.z = dz * rstd * sv.z + bv.z;
    o.w = dw * rstd * sv.w + bv.w;
    ((float4*)(h + (size_t)tok * 128))[lane] = o;
}

// ---------------------------------------------------------------------------
// Attention: one block per (b,h). K,V cached in padded shared memory.
// Warp per query: scores in registers (9 per lane), softmax via warp reduce,
// P broadcast through shared, output accumulated with lane==d.
// ---------------------------------------------------------------------------
#define ATT_SMEM ((2 * 257 * 33 + 8 * 264) * 4)

__global__ __launch_bounds__(256)
void attn_kernel(const float* __restrict__ qkv, float* __restrict__ o)
{
    extern __shared__ float sm[];
    float* Ks = sm;                 // [257][33]
    float* Vs = sm + 257 * 33;      // [257][33]
    float* Ps = sm + 2 * 257 * 33;  // [8][264]
    int b = blockIdx.x, h = blockIdx.y;
    int tid = threadIdx.x, w = tid >> 5, lane = tid & 31;
    const float* base = qkv + (size_t)b * NTOK * 384 + h * 32;

    for (int i = tid; i < 257 * 32; i += 256) {
        int m = i >> 5, d = i & 31;
        Ks[m * 33 + d] = base[(size_t)m * 384 + 128 + d];
        Vs[m * 33 + d] = base[(size_t)m * 384 + 256 + d];
    }
    __syncthreads();

    const float scale = 0.17677669529663687f;  // 1/sqrt(32)
    for (int n = w; n < NTOK; n += 8) {
        float qd = base[(size_t)n * 384 + lane];
        float sc[9];
        #pragma unroll
        for (int j = 0; j < 9; j++) sc[j] = 0.f;
        #pragma unroll
        for (int d = 0; d < 32; d++) {
            float qv = __shfl_sync(0xffffffffu, qd, d);
            #pragma unroll
            for (int j = 0; j < 8; j++)
                sc[j] += qv * Ks[(lane + 32 * j) * 33 + d];
            if (lane == 0) sc[8] += qv * Ks[256 * 33 + d];
        }
        // softmax over 257 entries (lane m = lane + 32*j; j==8 only lane 0)
        float mx = -1e30f;
        #pragma unroll
        for (int j = 0; j < 9; j++) {
            bool valid = (lane + 32 * j) < NTOK;
            sc[j] = valid ? sc[j] * scale : -1e30f;
            mx = fmaxf(mx, sc[j]);
        }
        mx = warp_max(mx);
        float lsum = 0.f;
        #pragma unroll
        for (int j = 0; j < 9; j++) {
            bool valid = (lane + 32 * j) < NTOK;
            sc[j] = valid ? __expf(sc[j] - mx) : 0.f;
            lsum += sc[j];
        }
        float inv = 1.f / warp_sum(lsum);
        #pragma unroll
        for (int j = 0; j < 9; j++) {
            int m = lane + 32 * j;
            if (m < NTOK) Ps[w * 264 + m] = sc[j] * inv;
        }
        __syncwarp();
        float acc = 0.f;
        #pragma unroll 4
        for (int m = 0; m < NTOK; m++)
            acc += Ps[w * 264 + m] * Vs[m * 33 + lane];
        o[((size_t)b * NTOK + n) * 128 + h * 32 + lane] = acc;
        __syncwarp();
    }
}

// ---------------------------------------------------------------------------
// Head: final LN (eps 1e-6) on token 0 of each batch, out_feat + fc.
// out layout: d_out[0:128) = out (64x2), d_out[128:8320) = out_feat (64x128)
// ---------------------------------------------------------------------------
__global__ __launch_bounds__(128)
void head_kernel(const float* __restrict__ x, const float* __restrict__ fns,
                 const float* __restrict__ fnb, const float* __restrict__ fcw,
                 const float* __restrict__ fcb, float* __restrict__ out)
{
    __shared__ float red[4];
    __shared__ float fsh[128];
    int b = blockIdx.x, t = threadIdx.x, w = t >> 5, lane = t & 31;
    float v = x[(size_t)b * NTOK * 128 + t];

    float s = warp_sum(v);
    if (lane == 0) red[w] = s;
    __syncthreads();
    float mean = (red[0] + red[1] + red[2] + red[3]) * (1.f / 128.f);
    __syncthreads();
    float d = v - mean;
    float sq = warp_sum(d * d);
    if (lane == 0) red[w] = sq;
    __syncthreads();
    float var = (red[0] + red[1] + red[2] + red[3]) * (1.f / 128.f);
    float rstd = rsqrtf(var + 1e-6f);
    float f = d * rstd * fns[t] + fnb[t];
    out[128 + (size_t)b * 128 + t] = f;
    fsh[t] = f;
    __syncthreads();
    if (t < 2) {
        float a = fcb[t];
        for (int e = 0; e < 128; e++) a += fsh[e] * fcw[t * 128 + e];
        out[b * 2 + t] = a;
    }
}

// ---------------------------------------------------------------------------
extern "C" void kernel_launch(void* const* d_in, const int* in_sizes, int n_in,
                              void* d_out, int out_size)
{
    const float* feat    = (const float*)d_in[0];
    const float* conv_w  = (const float*)d_in[1];
    const float* conv_b  = (const float*)d_in[2];
    const float* pos_emb = (const float*)d_in[3];
    const float* cls_tok = (const float*)d_in[4];
    const float* ln1_s   = (const float*)d_in[5];
    const float* ln1_b   = (const float*)d_in[6];
    const float* qkv_w   = (const float*)d_in[7];
    const float* qkv_b   = (const float*)d_in[8];
    const float* proj_w  = (const float*)d_in[9];
    const float* proj_b  = (const float*)d_in[10];
    const float* ln2_s   = (const float*)d_in[11];
    const float* ln2_b   = (const float*)d_in[12];
    const float* ffn1_w  = (const float*)d_in[13];
    const float* ffn1_b  = (const float*)d_in[14];
    const float* ffn2_w  = (const float*)d_in[15];
    const float* ffn2_b  = (const float*)d_in[16];
    const float* fn_s    = (const float*)d_in[17];
    const float* fn_b    = (const float*)d_in[18];
    const float* fc_w    = (const float*)d_in[19];
    const float* fc_b    = (const float*)d_in[20];
    float* out = (float*)d_out;

    float *px, *ph, *pq, *po, *pf;
    cudaGetSymbolAddress((void**)&px, g_x);
    cudaGetSymbolAddress((void**)&ph, g_h);
    cudaGetSymbolAddress((void**)&pq, g_qkv);
    cudaGetSymbolAddress((void**)&po, g_o);
    cudaGetSymbolAddress((void**)&pf, g_ffn);

    cudaFuncSetAttribute(attn_kernel, cudaFuncAttributeMaxDynamicSharedMemorySize, ATT_SMEM);

    cls_kernel<<<BATCH, 128>>>(cls_tok, pos_emb, px);
    conv_kernel<<<dim3(2, 256), 256>>>(feat, conv_w, conv_b, pos_emb, px);

    for (int l = 0; l < 12; l++) {
        ln_kernel<<<TOKENS / 8, 256>>>(px, ph, ln1_s + l * 128, ln1_b + l * 128, 1e-5f);
        gemm_kernel<0><<<dim3(6, TOKENS / 64), 256>>>(
            ph, qkv_w + (size_t)l * 384 * 128, qkv_b + l * 384, nullptr, pq,
            TOKENS, 384, 128);
        attn_kernel<<<dim3(BATCH, 4), 256, ATT_SMEM>>>(pq, po);
        gemm_kernel<2><<<dim3(2, TOKENS / 64), 256>>>(
            po, proj_w + (size_t)l * 128 * 128, proj_b + l * 128, px, px,
            TOKENS, 128, 128);
        ln_kernel<<<TOKENS / 8, 256>>>(px, ph, ln2_s + l * 128, ln2_b + l * 128, 1e-5f);
        gemm_kernel<1><<<dim3(8, TOKENS / 64), 256>>>(
            ph, ffn1_w + (size_t)l * 512 * 128, ffn1_b + l * 512, nullptr, pf,
            TOKENS, 512, 128);
        gemm_kernel<2><<<dim3(2, TOKENS / 64), 256>>>(
            pf, ffn2_w + (size_t)l * 128 * 512, ffn2_b + l * 128, px, px,
            TOKENS, 128, 512);
    }

    head_kernel<<<BATCH, 128>>>(px, fn_s, fn_b, fc_w, fc_b, out);
}

// round 3
// speedup vs baseline: 2.0346x; 2.0346x over previous
#include <cuda_runtime.h>
#include <math.h>
#include <stdint.h>

// ---------------------------------------------------------------------------
// Shapes (fixed): L=12, E=128, H=4, D=32, F=512, B=64, CIN=256, N=257
// Tokens T = B*N = 16448 = 64 * 257
// ---------------------------------------------------------------------------
#define TOKENS 16448
#define NTOK 257
#define BATCH 64

// scratch (device globals; allocation is forbidden)
__device__ float g_x  [TOKENS * 128];   // residual stream
__device__ float g_h  [TOKENS * 128];   // post-LN
__device__ float g_qkv[TOKENS * 384];
__device__ float g_o  [TOKENS * 128];   // attention output
__device__ float g_ffn[TOKENS * 512];   // ffn hidden

__device__ __forceinline__ float warp_sum(float v) {
    #pragma unroll
    for (int o = 16; o; o >>= 1) v += __shfl_xor_sync(0xffffffffu, v, o);
    return v;
}
__device__ __forceinline__ float warp_max(float v) {
    #pragma unroll
    for (int o = 16; o; o >>= 1) v = fmaxf(v, __shfl_xor_sync(0xffffffffu, v, o));
    return v;
}

__device__ __forceinline__ uint32_t to_tf32(float f) {
    uint32_t u;
    asm("cvt.rna.tf32.f32 %0, %1;" : "=r"(u) : "f"(f));
    return u;
}

// D = A(16x8, row) * B(8x8, col) + D, tf32 in, f32 accum
__device__ __forceinline__ void mma_tf32(float c[4], const uint32_t a[4], const uint32_t b[2]) {
    asm volatile(
        "mma.sync.aligned.m16n8k8.row.col.f32.tf32.tf32.f32 "
        "{%0,%1,%2,%3}, {%4,%5,%6,%7}, {%8,%9}, {%0,%1,%2,%3};"
        : "+f"(c[0]), "+f"(c[1]), "+f"(c[2]), "+f"(c[3])
        : "r"(a[0]), "r"(a[1]), "r"(a[2]), "r"(a[3]), "r"(b[0]), "r"(b[1]));
}

// ---------------------------------------------------------------------------
// Tensor-core GEMM: C[M,N] = A[M,K] @ W[N,K]^T + bias, fused epilogue.
// MODE 0: +bias   MODE 1: gelu(+bias)   MODE 2: +bias + residual
// Block tile 64x128, K-chunk 32. 256 threads = 8 warps in 2x4 (each 32x32).
// M%64==0, N%128==0, K%32==0 for all call sites.
// ---------------------------------------------------------------------------
#define SK 36   // padded k-stride (bank = (4g+c)%32 -> conflict-free frags)

template <int MODE>
__global__ __launch_bounds__(256)
void gemm_mma(const float* __restrict__ A, const float* __restrict__ W,
              const float* __restrict__ bias, const float* __restrict__ res,
              float* __restrict__ C, int M, int N, int K)
{
    __shared__ uint32_t As[64][SK];
    __shared__ uint32_t Bs[128][SK];
    const int tid = threadIdx.x;
    const int lane = tid & 31, wid = tid >> 5;
    const int warp_m = wid >> 2, warp_n = wid & 3;
    const int m0 = blockIdx.y * 64, n0 = blockIdx.x * 128;
    const int g = lane >> 2, cl = lane & 3;

    float acc[2][4][4];
    #pragma unroll
    for (int i = 0; i < 2; i++)
        #pragma unroll
        for (int j = 0; j < 4; j++)
            #pragma unroll
            for (int r = 0; r < 4; r++) acc[i][j][r] = 0.f;

    for (int k0 = 0; k0 < K; k0 += 32) {
        // load A 64x32 (2 float4/thread)
        #pragma unroll
        for (int it = 0; it < 2; it++) {
            int e = tid + it * 256;
            int row = e >> 3, c4 = (e & 7) * 4;
            float4 v = *(const float4*)(A + (size_t)(m0 + row) * K + k0 + c4);
            As[row][c4 + 0] = to_tf32(v.x);
            As[row][c4 + 1] = to_tf32(v.y);
            As[row][c4 + 2] = to_tf32(v.z);
            As[row][c4 + 3] = to_tf32(v.w);
        }
        // load B 128x32 (4 float4/thread)
        #pragma unroll
        for (int it = 0; it < 4; it++) {
            int e = tid + it * 256;
            int row = e >> 3, c4 = (e & 7) * 4;
            float4 v = *(const float4*)(W + (size_t)(n0 + row) * K + k0 + c4);
            Bs[row][c4 + 0] = to_tf32(v.x);
            Bs[row][c4 + 1] = to_tf32(v.y);
            Bs[row][c4 + 2] = to_tf32(v.z);
            Bs[row][c4 + 3] = to_tf32(v.w);
        }
        __syncthreads();

        #pragma unroll
        for (int ks = 0; ks < 4; ks++) {
            const int kk = ks * 8;
            uint32_t af[2][4], bf[4][2];
            #pragma unroll
            for (int mt = 0; mt < 2; mt++) {
                int r = warp_m * 32 + mt * 16 + g;
                af[mt][0] = As[r][kk + cl];
                af[mt][1] = As[r + 8][kk + cl];
                af[mt][2] = As[r][kk + 4 + cl];
                af[mt][3] = As[r + 8][kk + 4 + cl];
            }
            #pragma unroll
            for (int nt = 0; nt < 4; nt++) {
                int n = warp_n * 32 + nt * 8 + g;
                bf[nt][0] = Bs[n][kk + cl];
                bf[nt][1] = Bs[n][kk + 4 + cl];
            }
            #pragma unroll
            for (int mt = 0; mt < 2; mt++)
                #pragma unroll
                for (int nt = 0; nt < 4; nt++)
                    mma_tf32(acc[mt][nt], af[mt], bf[nt]);
        }
        __syncthreads();
    }

    // epilogue
    #pragma unroll
    for (int mt = 0; mt < 2; mt++) {
        int r = m0 + warp_m * 32 + mt * 16 + g;
        #pragma unroll
        for (int nt = 0; nt < 4; nt++) {
            int n = n0 + warp_n * 32 + nt * 8 + cl * 2;
            float b0 = bias[n], b1 = bias[n + 1];
            float v[4] = {acc[mt][nt][0] + b0, acc[mt][nt][1] + b1,
                          acc[mt][nt][2] + b0, acc[mt][nt][3] + b1};
            if (MODE == 1) {
                #pragma unroll
                for (int i = 0; i < 4; i++)
                    v[i] = v[i] * 0.5f * (1.0f + erff(v[i] * 0.70710678118654752f));
            }
            if (MODE == 2) {
                float2 r0 = *(const float2*)(res + (size_t)r * N + n);
                float2 r1 = *(const float2*)(res + (size_t)(r + 8) * N + n);
                v[0] += r0.x; v[1] += r0.y; v[2] += r1.x; v[3] += r1.y;
            }
            *(float2*)(C + (size_t)r * N + n)       = make_float2(v[0], v[1]);
            *(float2*)(C + (size_t)(r + 8) * N + n) = make_float2(v[2], v[3]);
        }
    }
}

// ---------------------------------------------------------------------------
// Conv 3x3 s2 p1 as implicit GEMM on tensor cores: M=16384, N=128, K=2304.
// Epilogue fuses conv bias + positional embedding, writes token buffer.
// ---------------------------------------------------------------------------
__global__ __launch_bounds__(256)
void conv_mma(const float* __restrict__ feat, const float* __restrict__ W,
              const float* __restrict__ cb, const float* __restrict__ pos,
              float* __restrict__ x)
{
    __shared__ uint32_t As[64][SK];
    __shared__ uint32_t Bs[128][SK];
    const int K = 2304;
    const int tid = threadIdx.x;
    const int lane = tid & 31, wid = tid >> 5;
    const int warp_m = wid >> 2, warp_n = wid & 3;
    const int m0 = blockIdx.y * 64;
    const int g = lane >> 2, cl = lane & 3;

    float acc[2][4][4];
    #pragma unroll
    for (int i = 0; i < 2; i++)
        #pragma unroll
        for (int j = 0; j < 4; j++)
            #pragma unroll
            for (int r = 0; r < 4; r++) acc[i][j][r] = 0.f;

    for (int k0 = 0; k0 < K; k0 += 32) {
        // implicit im2col A load (scalar gather)
        #pragma unroll
        for (int it = 0; it < 8; it++) {
            int e = tid + it * 256;
            int ml = e >> 5, kl = e & 31;
            int m = m0 + ml;
            int k = k0 + kl;
            int b = m >> 8, p = m & 255;
            int y = p >> 4, xx = p & 15;
            int c = k / 9, rr = k - c * 9;
            int ky = rr / 3, kx = rr - ky * 3;
            int iy = y * 2 - 1 + ky;
            int ix = xx * 2 - 1 + kx;
            float v = 0.f;
            if (iy >= 0 && iy < 32 && ix >= 0 && ix < 32)
                v = feat[(((size_t)b * 256 + c) * 32 + iy) * 32 + ix];
            As[ml][kl] = to_tf32(v);
        }
        #pragma unroll
        for (int it = 0; it < 4; it++) {
            int e = tid + it * 256;
            int row = e >> 3, c4 = (e & 7) * 4;
            float4 v = *(const float4*)(W + (size_t)row * K + k0 + c4);
            Bs[row][c4 + 0] = to_tf32(v.x);
            Bs[row][c4 + 1] = to_tf32(v.y);
            Bs[row][c4 + 2] = to_tf32(v.z);
            Bs[row][c4 + 3] = to_tf32(v.w);
        }
        __syncthreads();

        #pragma unroll
        for (int ks = 0; ks < 4; ks++) {
            const int kk = ks * 8;
            uint32_t af[2][4], bf[4][2];
            #pragma unroll
            for (int mt = 0; mt < 2; mt++) {
                int r = warp_m * 32 + mt * 16 + g;
                af[mt][0] = As[r][kk + cl];
                af[mt][1] = As[r + 8][kk + cl];
                af[mt][2] = As[r][kk + 4 + cl];
                af[mt][3] = As[r + 8][kk + 4 + cl];
            }
            #pragma unroll
            for (int nt = 0; nt < 4; nt++) {
                int n = warp_n * 32 + nt * 8 + g;
                bf[nt][0] = Bs[n][kk + cl];
                bf[nt][1] = Bs[n][kk + 4 + cl];
            }
            #pragma unroll
            for (int mt = 0; mt < 2; mt++)
                #pragma unroll
                for (int nt = 0; nt < 4; nt++)
                    mma_tf32(acc[mt][nt], af[mt], bf[nt]);
        }
        __syncthreads();
    }

    #pragma unroll
    for (int mt = 0; mt < 2; mt++) {
        int r = m0 + warp_m * 32 + mt * 16 + g;
        #pragma unroll
        for (int rr = 0; rr < 2; rr++) {
            int m = r + rr * 8;
            int b = m >> 8, p = m & 255;
            float* dst = x + ((size_t)b * NTOK + p + 1) * 128;
            const float* pp = pos + (size_t)(p + 1) * 128;
            #pragma unroll
            for (int nt = 0; nt < 4; nt++) {
                int n = warp_n * 32 + nt * 8 + cl * 2;
                float v0 = acc[mt][nt][rr * 2 + 0] + cb[n] + pp[n];
                float v1 = acc[mt][nt][rr * 2 + 1] + cb[n + 1] + pp[n + 1];
                *(float2*)(dst + n) = make_float2(v0, v1);
            }
        }
    }
}

// cls token rows: x[b,0,:] = cls + pos[0]
__global__ void cls_kernel(const float* __restrict__ cls,
                           const float* __restrict__ pos, float* __restrict__ x)
{
    int b = blockIdx.x, e = threadIdx.x;
    x[(size_t)b * NTOK * 128 + e] = cls[e] + pos[e];
}

// ---------------------------------------------------------------------------
// LayerNorm over E=128: 1 warp per token, float4 lanes.
// ---------------------------------------------------------------------------
__global__ __launch_bounds__(256)
void ln_kernel(const float* __restrict__ x, float* __restrict__ h,
               const float* __restrict__ s, const float* __restrict__ b, float eps)
{
    int tok = blockIdx.x * 8 + (threadIdx.x >> 5);
    int lane = threadIdx.x & 31;
    if (tok >= TOKENS) return;
    const float4* xr = (const float4*)(x + (size_t)tok * 128);
    float4 v = xr[lane];
    float mean = warp_sum(v.x + v.y + v.z + v.w) * (1.f / 128.f);
    float dx = v.x - mean, dy = v.y - mean, dz = v.z - mean, dw = v.w - mean;
    float var = warp_sum(dx * dx + dy * dy + dz * dz + dw * dw) * (1.f / 128.f);
    float rstd = rsqrtf(var + eps);
    float4 sv = ((const float4*)s)[lane];
    float4 bv = ((const float4*)b)[lane];
    float4 o;
    o.x = dx * rstd * sv.x + bv.x;
    o.y = dy * rstd * sv.y + bv.y;
    o.z = dz * rstd * sv.z + bv.z;
    o.w = dw * rstd * sv.w + bv.w;
    ((float4*)(h + (size_t)tok * 128))[lane] = o;
}

// ---------------------------------------------------------------------------
// Attention: block per (b,h,z). K,V cached in smem. 4 queries per warp:
// K-tile LDS amortized 4x in QK, V LDS amortized 4x in PV.
// grid.z=3, 3 query-tiles of 32 per z (9 tiles cover 257).
// ---------------------------------------------------------------------------
#define ATT_SMEM ((2 * 257 * 33 + 32 * 264) * 4)

__global__ __launch_bounds__(256)
void attn_kernel(const float* __restrict__ qkv, float* __restrict__ o)
{
    extern __shared__ float sm[];
    float* Ks = sm;                 // [257][33]
    float* Vs = sm + 257 * 33;      // [257][33]
    float* Ps = sm + 2 * 257 * 33;  // [32][264]
    int b = blockIdx.x, h = blockIdx.y, z = blockIdx.z;
    int tid = threadIdx.x, w = tid >> 5, lane = tid & 31;
    const float* base = qkv + (size_t)b * NTOK * 384 + h * 32;

    for (int i = tid; i < 257 * 32; i += 256) {
        int m = i >> 5, d = i & 31;
        Ks[m * 33 + d] = base[(size_t)m * 384 + 128 + d];
        Vs[m * 33 + d] = base[(size_t)m * 384 + 256 + d];
    }
    __syncthreads();

    const float scale = 0.17677669529663687f;  // 1/sqrt(32)
    for (int t = z * 3; t < z * 3 + 3; t++) {
        if (t * 32 >= NTOK) break;
        int qbase = t * 32 + w * 4;
        float qd[4];
        bool val[4];
        #pragma unroll
        for (int qq = 0; qq < 4; qq++) {
            int n = qbase + qq;
            val[qq] = n < NTOK;
            qd[qq] = val[qq] ? base[(size_t)n * 384 + lane] : 0.f;
        }
        float sc[4][9];
        #pragma unroll
        for (int qq = 0; qq < 4; qq++)
            #pragma unroll
            for (int j = 0; j < 9; j++) sc[qq][j] = 0.f;

        #pragma unroll 4
        for (int d = 0; d < 32; d++) {
            float qv[4];
            #pragma unroll
            for (int qq = 0; qq < 4; qq++)
                qv[qq] = __shfl_sync(0xffffffffu, qd[qq], d);
            #pragma unroll
            for (int j = 0; j < 8; j++) {
                float kv = Ks[(lane + 32 * j) * 33 + d];
                #pragma unroll
                for (int qq = 0; qq < 4; qq++) sc[qq][j] += qv[qq] * kv;
            }
            float kv8 = Ks[256 * 33 + d];  // only lane 0's m=256 is valid
            #pragma unroll
            for (int qq = 0; qq < 4; qq++) sc[qq][8] += qv[qq] * kv8;
        }

        #pragma unroll
        for (int qq = 0; qq < 4; qq++) {
            float mx = -1e30f;
            #pragma unroll
            for (int j = 0; j < 9; j++) {
                bool ok = (lane + 32 * j) < NTOK;
                sc[qq][j] = ok ? sc[qq][j] * scale : -1e30f;
                mx = fmaxf(mx, sc[qq][j]);
            }
            mx = warp_max(mx);
            float lsum = 0.f;
            #pragma unroll
            for (int j = 0; j < 9; j++) {
                bool ok = (lane + 32 * j) < NTOK;
                sc[qq][j] = ok ? __expf(sc[qq][j] - mx) : 0.f;
                lsum += sc[qq][j];
            }
            float inv = 1.f / warp_sum(lsum);
            #pragma unroll
            for (int j = 0; j < 9; j++) {
                int m = lane + 32 * j;
                if (m < NTOK) Ps[(w * 4 + qq) * 264 + m] = sc[qq][j] * inv;
            }
        }
        __syncwarp();

        float acc[4] = {0.f, 0.f, 0.f, 0.f};
        #pragma unroll 4
        for (int m = 0; m < NTOK; m++) {
            float v = Vs[m * 33 + lane];
            #pragma unroll
            for (int qq = 0; qq < 4; qq++)
                acc[qq] += Ps[(w * 4 + qq) * 264 + m] * v;
        }
        #pragma unroll
        for (int qq = 0; qq < 4; qq++)
            if (val[qq])
                o[((size_t)b * NTOK + qbase + qq) * 128 + h * 32 + lane] = acc[qq];
        __syncwarp();
    }
}

// ---------------------------------------------------------------------------
// Head: final LN (eps 1e-6) on token 0 of each batch, out_feat + fc.
// out layout: d_out[0:128) = out (64x2), d_out[128:8320) = out_feat (64x128)
// ---------------------------------------------------------------------------
__global__ __launch_bounds__(128)
void head_kernel(const float* __restrict__ x, const float* __restrict__ fns,
                 const float* __restrict__ fnb, const float* __restrict__ fcw,
                 const float* __restrict__ fcb, float* __restrict__ out)
{
    __shared__ float red[4];
    __shared__ float fsh[128];
    int b = blockIdx.x, t = threadIdx.x, w = t >> 5, lane = t & 31;
    float v = x[(size_t)b * NTOK * 128 + t];

    float s = warp_sum(v);
    if (lane == 0) red[w] = s;
    __syncthreads();
    float mean = (red[0] + red[1] + red[2] + red[3]) * (1.f / 128.f);
    __syncthreads();
    float d = v - mean;
    float sq = warp_sum(d * d);
    if (lane == 0) red[w] = sq;
    __syncthreads();
    float var = (red[0] + red[1] + red[2] + red[3]) * (1.f / 128.f);
    float rstd = rsqrtf(var + 1e-6f);
    float f = d * rstd * fns[t] + fnb[t];
    out[128 + (size_t)b * 128 + t] = f;
    fsh[t] = f;
    __syncthreads();
    if (t < 2) {
        float a = fcb[t];
        for (int e = 0; e < 128; e++) a += fsh[e] * fcw[t * 128 + e];
        out[b * 2 + t] = a;
    }
}

// ---------------------------------------------------------------------------
extern "C" void kernel_launch(void* const* d_in, const int* in_sizes, int n_in,
                              void* d_out, int out_size)
{
    const float* feat    = (const float*)d_in[0];
    const float* conv_w  = (const float*)d_in[1];
    const float* conv_b  = (const float*)d_in[2];
    const float* pos_emb = (const float*)d_in[3];
    const float* cls_tok = (const float*)d_in[4];
    const float* ln1_s   = (const float*)d_in[5];
    const float* ln1_b   = (const float*)d_in[6];
    const float* qkv_w   = (const float*)d_in[7];
    const float* qkv_b   = (const float*)d_in[8];
    const float* proj_w  = (const float*)d_in[9];
    const float* proj_b  = (const float*)d_in[10];
    const float* ln2_s   = (const float*)d_in[11];
    const float* ln2_b   = (const float*)d_in[12];
    const float* ffn1_w  = (const float*)d_in[13];
    const float* ffn1_b  = (const float*)d_in[14];
    const float* ffn2_w  = (const float*)d_in[15];
    const float* ffn2_b  = (const float*)d_in[16];
    const float* fn_s    = (const float*)d_in[17];
    const float* fn_b    = (const float*)d_in[18];
    const float* fc_w    = (const float*)d_in[19];
    const float* fc_b    = (const float*)d_in[20];
    float* out = (float*)d_out;

    float *px, *ph, *pq, *po, *pf;
    cudaGetSymbolAddress((void**)&px, g_x);
    cudaGetSymbolAddress((void**)&ph, g_h);
    cudaGetSymbolAddress((void**)&pq, g_qkv);
    cudaGetSymbolAddress((void**)&po, g_o);
    cudaGetSymbolAddress((void**)&pf, g_ffn);

    cudaFuncSetAttribute(attn_kernel, cudaFuncAttributeMaxDynamicSharedMemorySize, ATT_SMEM);

    cls_kernel<<<BATCH, 128>>>(cls_tok, pos_emb, px);
    conv_mma<<<dim3(1, 256), 256>>>(feat, conv_w, conv_b, pos_emb, px);

    for (int l = 0; l < 12; l++) {
        ln_kernel<<<TOKENS / 8, 256>>>(px, ph, ln1_s + l * 128, ln1_b + l * 128, 1e-5f);
        gemm_mma<0><<<dim3(3, 257), 256>>>(
            ph, qkv_w + (size_t)l * 384 * 128, qkv_b + l * 384, nullptr, pq,
            TOKENS, 384, 128);
        attn_kernel<<<dim3(BATCH, 4, 3), 256, ATT_SMEM>>>(pq, po);
        gemm_mma<2><<<dim3(1, 257), 256>>>(
            po, proj_w + (size_t)l * 128 * 128, proj_b + l * 128, px, px,
            TOKENS, 128, 128);
        ln_kernel<<<TOKENS / 8, 256>>>(px, ph, ln2_s + l * 128, ln2_b + l * 128, 1e-5f);
        gemm_mma<1><<<dim3(4, 257), 256>>>(
            ph, ffn1_w + (size_t)l * 512 * 128, ffn1_b + l * 512, nullptr, pf,
            TOKENS, 512, 128);
        gemm_mma<2><<<dim3(1, 257), 256>>>(
            pf, ffn2_w + (size_t)l * 128 * 512, ffn2_b + l * 128, px, px,
            TOKENS, 128, 512);
    }

    head_kernel<<<BATCH, 128>>>(px, fn_s, fn_b, fc_w, fc_b, out);
}